// round 2
// baseline (speedup 1.0000x reference)
#include <cuda_runtime.h>

// B3-spline à-trous undecimated wavelet transform, J=3, fused single kernel.
// Input  x: (B, 1024, 1024) fp32.  Output: (B, 4, 1024, 1024) = [w1, w2, w3, c3].
//
// Tile = 64x64 output pixels per CTA. Cascaded halo: level d=1 needs +-2,
// d=2 +-4, d=4 +-8 => total +-14. All intermediates live in shared memory.
// Because the 5-tap kernel is symmetric, conv(reflect(x)) == reflect(conv(x)),
// so computing halo values of c1/c2 from a reflect-loaded c0 region exactly
// matches the reference's per-level reflect padding.
//
// Every separable 1-D pass has the same canonical form:
//    dst[c][r] = sum_k w_k * src[r + k*d][c]      (store transposed)
// so the conv direction alternates automatically (y, x, y, x, ...).
// Each thread produces 8 consecutive outputs along r from 8+4d register-held
// loads (sliding window) -> smem load factor (8+4d)/8 instead of 5.
// Buffer stride 93 (odd) => both lane-contiguous reads (fixed r, lanes along c)
// and transposed column writes (lanes along c => rows of dst) are conflict-free.

#define IMG_H 1024
#define IMG_W 1024
#define TILE 64
#define STRIDE 93               // odd stride, >= 92 cols
#define BUF_FLOATS (92 * STRIDE)
#define SMEM_BYTES (3 * BUF_FLOATS * 4)

#define W0 0.0625f
#define W1 0.25f
#define W2 0.375f

__device__ __forceinline__ int refl(int i) {
    if (i < 0) return -i;
    if (i >= IMG_H) return 2 * IMG_H - 2 - i;
    return i;
}

// Plain pass (used for the t = conv_along_rows intermediates).
// RR: output rows (multiple of 8), RC: output cols. D: dilation.
template <int D, int RR, int RC>
__device__ __forceinline__ void tpass(const float* __restrict__ src,
                                      float* __restrict__ dst,
                                      int warp, int lane) {
    constexpr int GC = (RC + 31) / 32;
    constexpr int GR = RR / 8;
    constexpr int L = 8 + 4 * D;
    for (int g = warp; g < GC * GR; g += 8) {
        int c  = (g % GC) * 32 + lane;
        int r0 = (g / GC) * 8;
        if (c >= RC) continue;
        float v[L];
#pragma unroll
        for (int i = 0; i < L; i++) v[i] = src[(r0 + i) * STRIDE + c];
#pragma unroll
        for (int i = 0; i < 8; i++) {
            dst[c * STRIDE + r0 + i] =
                W0 * (v[i] + v[i + 4 * D]) + W1 * (v[i + D] + v[i + 3 * D]) +
                W2 * v[i + 2 * D];
        }
    }
}

// c-pass: completes level j (second 1-D conv), optionally stores c_j to smem,
// and writes w_j = c_{j-1} - c_j (and c_J on the last level) to global memory.
// HALO: tile offset inside the output region. PO: index offset into prev buf.
template <int D, int RR, int RC, int HALO, int PO, bool STORE, bool LAST>
__device__ __forceinline__ void cpass(const float* __restrict__ src,
                                      float* __restrict__ dst,
                                      const float* __restrict__ prev,
                                      float* __restrict__ gw,   // w_j plane @ tile origin
                                      float* __restrict__ gc,   // c_J plane @ tile origin
                                      int warp, int lane) {
    constexpr int GC = (RC + 31) / 32;
    constexpr int GR = RR / 8;
    constexpr int L = 8 + 4 * D;
    for (int g = warp; g < GC * GR; g += 8) {
        int c  = (g % GC) * 32 + lane;
        int r0 = (g / GC) * 8;
        if (c >= RC) continue;
        float v[L];
#pragma unroll
        for (int i = 0; i < L; i++) v[i] = src[(r0 + i) * STRIDE + c];
        float o[8];
#pragma unroll
        for (int i = 0; i < 8; i++) {
            o[i] = W0 * (v[i] + v[i + 4 * D]) + W1 * (v[i + D] + v[i + 3 * D]) +
                   W2 * v[i + 2 * D];
            if (STORE) dst[c * STRIDE + r0 + i] = o[i];
        }
        // fused detail-coefficient output (r indexes x, c indexes y here)
        if (c >= HALO && c < HALO + TILE) {
            int yt = c - HALO;
            const float* pr = prev + (c + PO) * STRIDE + r0 + PO;
#pragma unroll
            for (int q = 0; q < 2; q++) {
                int i0 = q * 4;
                int xt = r0 + i0 - HALO;
                if (xt >= 0 && xt + 4 <= TILE) {
                    float4 wv;
                    wv.x = pr[i0 + 0] - o[i0 + 0];
                    wv.y = pr[i0 + 1] - o[i0 + 1];
                    wv.z = pr[i0 + 2] - o[i0 + 2];
                    wv.w = pr[i0 + 3] - o[i0 + 3];
                    *(float4*)(gw + (size_t)yt * IMG_W + xt) = wv;
                    if (LAST) {
                        float4 cv = make_float4(o[i0], o[i0 + 1], o[i0 + 2], o[i0 + 3]);
                        *(float4*)(gc + (size_t)yt * IMG_W + xt) = cv;
                    }
                }
            }
        }
    }
}

__global__ __launch_bounds__(256, 2)
void uwt_kernel(const float* __restrict__ x, float* __restrict__ out) {
    extern __shared__ float sm[];
    float* A  = sm;
    float* Bb = sm + BUF_FLOATS;
    float* Cc = sm + 2 * BUF_FLOATS;

    const int tid  = threadIdx.x;
    const int lane = tid & 31;
    const int warp = tid >> 5;
    const int tx0  = blockIdx.x * TILE;
    const int ty0  = blockIdx.y * TILE;
    const int b    = blockIdx.z;

    const float* xb = x + (size_t)b * IMG_H * IMG_W;

    // Load c0 region: 92x92, origin (ty0-14, tx0-14), reflect-padded.
    for (int r = warp; r < 92; r += 8) {
        const float* row = xb + (size_t)refl(ty0 - 14 + r) * IMG_W;
#pragma unroll
        for (int cg = 0; cg < 3; cg++) {
            int c = cg * 32 + lane;
            if (c < 92) A[r * STRIDE + c] = row[refl(tx0 - 14 + c)];
        }
    }
    __syncthreads();

    float* base = out + (size_t)b * 4 * IMG_H * IMG_W;
    float* w1p = base + 0 * (size_t)IMG_H * IMG_W + (size_t)ty0 * IMG_W + tx0;
    float* w2p = base + 1 * (size_t)IMG_H * IMG_W + (size_t)ty0 * IMG_W + tx0;
    float* w3p = base + 2 * (size_t)IMG_H * IMG_W + (size_t)ty0 * IMG_W + tx0;
    float* c3p = base + 3 * (size_t)IMG_H * IMG_W + (size_t)ty0 * IMG_W + tx0;

    // Level 1 (d=1): t1 = convY(c0) -> B (transposed); c1 = convX(t1) -> C; emit w1.
    tpass<1, 88, 92>(A, Bb, warp, lane);
    __syncthreads();
    cpass<1, 88, 88, 12, 2, true, false>(Bb, Cc, A, w1p, nullptr, warp, lane);
    __syncthreads();

    // Level 2 (d=2): t2 -> A (transposed); c2 -> B; emit w2.
    tpass<2, 80, 88>(Cc, A, warp, lane);
    __syncthreads();
    cpass<2, 80, 80, 8, 4, true, false>(A, Bb, Cc, w2p, nullptr, warp, lane);
    __syncthreads();

    // Level 3 (d=4): t3 -> C (transposed); c3 not stored; emit w3 and c3.
    tpass<4, 64, 80>(Bb, Cc, warp, lane);
    __syncthreads();
    cpass<4, 64, 64, 0, 8, false, true>(Cc, nullptr, Bb, w3p, c3p, warp, lane);
}

extern "C" void kernel_launch(void* const* d_in, const int* in_sizes, int n_in,
                              void* d_out, int out_size) {
    const float* x = (const float*)d_in[0];
    float* out = (float*)d_out;
    int batch = in_sizes[0] / (IMG_H * IMG_W);

    cudaFuncSetAttribute(uwt_kernel, cudaFuncAttributeMaxDynamicSharedMemorySize,
                         SMEM_BYTES);

    dim3 grid(IMG_W / TILE, IMG_H / TILE, batch);
    dim3 block(256);
    uwt_kernel<<<grid, block, SMEM_BYTES>>>(x, out);
}

// round 3
// speedup vs baseline: 1.1383x; 1.1383x over previous
#include <cuda_runtime.h>

// B3-spline à-trous undecimated wavelet transform, J=3, fused single kernel.
// Input  x: (B, 1024, 1024) fp32.  Output: (B, 4, 1024, 1024) = [w1, w2, w3, c3].
//
// Tile = 64x64 output pixels per CTA, cascaded halo 14 (2+4+8), all
// intermediates in shared memory (3 ping-pong buffers, 92x93 fp32).
// Symmetric taps => conv(reflect(x)) == reflect(conv(x)), so one reflect-padded
// load of c0 reproduces the reference's per-level reflect padding exactly.
//
// Each separable 1-D pass: dst[c][r] = sum_k w_k src[r+k*d][c] (transposed
// store), 8-way register coarsening along r. Stride 93 (odd) keeps both the
// lane-contiguous reads and the transposed column writes bank-conflict-free.
//
// R2: 512 threads/CTA (was 256) -> 32 warps/SM at 2 CTAs/SM; kernel was
// issue/latency-bound (occ 23.7%, issue 32.9%).

#define IMG_H 1024
#define IMG_W 1024
#define TILE 64
#define STRIDE 93
#define BUF_FLOATS (92 * STRIDE)
#define SMEM_BYTES (3 * BUF_FLOATS * 4)
#define NW 16                    // warps per CTA

#define W0 0.0625f
#define W1 0.25f
#define W2 0.375f

__device__ __forceinline__ int refl(int i) {
    if (i < 0) return -i;
    if (i >= IMG_H) return 2 * IMG_H - 2 - i;
    return i;
}

// Plain pass: t = conv along rows, stored transposed.
template <int D, int RR, int RC>
__device__ __forceinline__ void tpass(const float* __restrict__ src,
                                      float* __restrict__ dst,
                                      int warp, int lane) {
    constexpr int GC = (RC + 31) / 32;
    constexpr int GR = RR / 8;
    constexpr int L = 8 + 4 * D;
    for (int g = warp; g < GC * GR; g += NW) {
        int c  = (g % GC) * 32 + lane;
        int r0 = (g / GC) * 8;
        if (c >= RC) continue;
        float v[L];
#pragma unroll
        for (int i = 0; i < L; i++) v[i] = src[(r0 + i) * STRIDE + c];
#pragma unroll
        for (int i = 0; i < 8; i++) {
            dst[c * STRIDE + r0 + i] =
                W0 * (v[i] + v[i + 4 * D]) + W1 * (v[i + D] + v[i + 3 * D]) +
                W2 * v[i + 2 * D];
        }
    }
}

// c-pass: completes level j, optionally stores c_j to smem, and writes
// w_j = c_{j-1} - c_j (and c_J if LAST) to global memory as float4.
template <int D, int RR, int RC, int HALO, int PO, bool STORE, bool LAST>
__device__ __forceinline__ void cpass(const float* __restrict__ src,
                                      float* __restrict__ dst,
                                      const float* __restrict__ prev,
                                      float* __restrict__ gw,
                                      float* __restrict__ gc,
                                      int warp, int lane) {
    constexpr int GC = (RC + 31) / 32;
    constexpr int GR = RR / 8;
    constexpr int L = 8 + 4 * D;
    for (int g = warp; g < GC * GR; g += NW) {
        int c  = (g % GC) * 32 + lane;
        int r0 = (g / GC) * 8;
        if (c >= RC) continue;
        float v[L];
#pragma unroll
        for (int i = 0; i < L; i++) v[i] = src[(r0 + i) * STRIDE + c];
        float o[8];
#pragma unroll
        for (int i = 0; i < 8; i++) {
            o[i] = W0 * (v[i] + v[i + 4 * D]) + W1 * (v[i + D] + v[i + 3 * D]) +
                   W2 * v[i + 2 * D];
            if (STORE) dst[c * STRIDE + r0 + i] = o[i];
        }
        if (c >= HALO && c < HALO + TILE) {
            int yt = c - HALO;
            const float* pr = prev + (c + PO) * STRIDE + r0 + PO;
#pragma unroll
            for (int q = 0; q < 2; q++) {
                int i0 = q * 4;
                int xt = r0 + i0 - HALO;
                if (xt >= 0 && xt + 4 <= TILE) {
                    float4 wv;
                    wv.x = pr[i0 + 0] - o[i0 + 0];
                    wv.y = pr[i0 + 1] - o[i0 + 1];
                    wv.z = pr[i0 + 2] - o[i0 + 2];
                    wv.w = pr[i0 + 3] - o[i0 + 3];
                    *(float4*)(gw + (size_t)yt * IMG_W + xt) = wv;
                    if (LAST) {
                        float4 cv = make_float4(o[i0], o[i0 + 1], o[i0 + 2], o[i0 + 3]);
                        *(float4*)(gc + (size_t)yt * IMG_W + xt) = cv;
                    }
                }
            }
        }
    }
}

__global__ __launch_bounds__(32 * NW, 2)
void uwt_kernel(const float* __restrict__ x, float* __restrict__ out) {
    extern __shared__ float sm[];
    float* A  = sm;
    float* Bb = sm + BUF_FLOATS;
    float* Cc = sm + 2 * BUF_FLOATS;

    const int tid  = threadIdx.x;
    const int lane = tid & 31;
    const int warp = tid >> 5;
    const int tx0  = blockIdx.x * TILE;
    const int ty0  = blockIdx.y * TILE;
    const int b    = blockIdx.z;

    const float* xb = x + (size_t)b * IMG_H * IMG_W;

    // Load c0 region: 92x92, origin (ty0-14, tx0-14), reflect-padded.
    for (int r = warp; r < 92; r += NW) {
        const float* row = xb + (size_t)refl(ty0 - 14 + r) * IMG_W;
#pragma unroll
        for (int cg = 0; cg < 3; cg++) {
            int c = cg * 32 + lane;
            if (c < 92) A[r * STRIDE + c] = row[refl(tx0 - 14 + c)];
        }
    }
    __syncthreads();

    float* base = out + (size_t)b * 4 * IMG_H * IMG_W;
    float* w1p = base + 0 * (size_t)IMG_H * IMG_W + (size_t)ty0 * IMG_W + tx0;
    float* w2p = base + 1 * (size_t)IMG_H * IMG_W + (size_t)ty0 * IMG_W + tx0;
    float* w3p = base + 2 * (size_t)IMG_H * IMG_W + (size_t)ty0 * IMG_W + tx0;
    float* c3p = base + 3 * (size_t)IMG_H * IMG_W + (size_t)ty0 * IMG_W + tx0;

    // Level 1 (d=1): t1 = convY(c0) -> B (transposed); c1 = convX(t1) -> C; w1.
    tpass<1, 88, 92>(A, Bb, warp, lane);
    __syncthreads();
    cpass<1, 88, 88, 12, 2, true, false>(Bb, Cc, A, w1p, nullptr, warp, lane);
    __syncthreads();

    // Level 2 (d=2): t2 -> A (transposed); c2 -> B; w2.
    tpass<2, 80, 88>(Cc, A, warp, lane);
    __syncthreads();
    cpass<2, 80, 80, 8, 4, true, false>(A, Bb, Cc, w2p, nullptr, warp, lane);
    __syncthreads();

    // Level 3 (d=4): t3 -> C (transposed); c3 not stored; w3 and c3.
    tpass<4, 64, 80>(Bb, Cc, warp, lane);
    __syncthreads();
    cpass<4, 64, 64, 0, 8, false, true>(Cc, nullptr, Bb, w3p, c3p, warp, lane);
}

extern "C" void kernel_launch(void* const* d_in, const int* in_sizes, int n_in,
                              void* d_out, int out_size) {
    const float* x = (const float*)d_in[0];
    float* out = (float*)d_out;
    int batch = in_sizes[0] / (IMG_H * IMG_W);

    cudaFuncSetAttribute(uwt_kernel, cudaFuncAttributeMaxDynamicSharedMemorySize,
                         SMEM_BYTES);

    dim3 grid(IMG_W / TILE, IMG_H / TILE, batch);
    dim3 block(32 * NW);
    uwt_kernel<<<grid, block, SMEM_BYTES>>>(x, out);
}